// round 11
// baseline (speedup 1.0000x reference)
#include <cuda_runtime.h>
#include <cuda_fp16.h>

#define NN 100000
#define EC 6400000
#define ED 400000
#define HH 8
#define FIN 5
#define BN_EPS 1e-5
#define L2_EPS 1e-12f
#define SB 512
#define NSLICE 8
#define FULLM 0xffffffffu
#define GSYNC 296   // 2 blocks/SM x 148 SMs; residency guaranteed by __launch_bounds__(256,2)

// ---------------- scratch ----------------
__device__ __align__(16) int g_csrc[EC];     // CSR src lists (by dst)
__device__ __align__(16) int g_csrd[ED];
__device__ int   g_cntc[NN];
__device__ int   g_cntd[NN];
__device__ int   g_curc[NN];
__device__ int   g_curd[NN];
__device__ int   g_rowc[NN];
__device__ int   g_rowd[NN];
__device__ int   g_bsumc[256];
__device__ int   g_bsumd[256];
__device__ __align__(16) __half g_zh[(NN + 1) * HH]; // fp16 gather payload
__device__ __align__(16) float  g_h[NN * HH];        // post-BN features
__device__ __align__(16) float  g_y[NN * HH];        // pre-BN activations
__device__ double   g_stats[5][NSLICE][16];
__device__ unsigned g_arrive[5];
__device__ int      g_mode;

// ---------------- init ----------------
__global__ void k_init() {
    int i = blockIdx.x * blockDim.x + threadIdx.x;
    if (i < NN) { g_cntc[i] = 0; g_cntd[i] = 0; g_curc[i] = 0; g_curd[i] = 0; }
    if (i < 5 * NSLICE * 16) ((double*)g_stats)[i] = 0.0;
    if (i < 5) g_arrive[i] = 0u;
}

// ---------------- int64 vs int32 edge dtype detection ----------------
__global__ void k_detect(const int* __restrict__ ei) {
    int lane = threadIdx.x;
    int v = ei[2 * lane + 1];
    unsigned ball = __ballot_sync(FULLM, v == 0);
    if (lane == 0) g_mode = (ball == FULLM) ? 1 : 0;
}

__device__ __forceinline__ void load_edge(const void* ei, int E, int e, int& src, int& dst) {
    if (g_mode) {
        const long long* p = (const long long*)ei;
        src = (int)p[e]; dst = (int)p[E + e];
    } else {
        const int* p = (const int*)ei;
        src = p[e]; dst = p[E + e];
    }
}

// ---------------- fused count over both edge sets ----------------
__global__ void k_count(const void* __restrict__ eic, const void* __restrict__ eid, int gEC) {
    long long b = blockIdx.x;
    if (b < gEC) {
        int e = (int)(b * blockDim.x + threadIdx.x);
        if (e < EC) {
            int src, dst; load_edge(eic, EC, e, src, dst);
            atomicAdd(&g_cntc[dst], 1);
        }
    } else {
        int e = (int)((b - gEC) * blockDim.x + threadIdx.x);
        if (e < ED) {
            int src, dst; load_edge(eid, ED, e, src, dst);
            atomicAdd(&g_cntd[dst], 1);
        }
    }
}

// ---------------- fused scans ----------------
__global__ void k_scan1() {
    __shared__ int sh[SB];
    int half = gridDim.x >> 1;
    bool isC = blockIdx.x < half;
    const int* cnt = isC ? g_cntc : g_cntd;
    int* rowp = isC ? g_rowc : g_rowd;
    int* bsum = isC ? g_bsumc : g_bsumd;
    int b = isC ? blockIdx.x : blockIdx.x - half;
    int tid = threadIdx.x;
    int g = b * SB + tid;
    int v = (g < NN) ? cnt[g] : 0;
    sh[tid] = v; __syncthreads();
#pragma unroll
    for (int o = 1; o < SB; o <<= 1) {
        int t = (tid >= o) ? sh[tid - o] : 0;
        __syncthreads();
        sh[tid] += t;
        __syncthreads();
    }
    if (g < NN) rowp[g] = sh[tid] - v;
    if (tid == SB - 1) bsum[b] = sh[SB - 1];
}
__global__ void k_scan2(int nb) {
    __shared__ int sh[256];
    int* bsum = (blockIdx.x == 0) ? g_bsumc : g_bsumd;
    int tid = threadIdx.x;
    int v = (tid < nb) ? bsum[tid] : 0;
    sh[tid] = v; __syncthreads();
#pragma unroll
    for (int o = 1; o < 256; o <<= 1) {
        int t = (tid >= o) ? sh[tid - o] : 0;
        __syncthreads();
        sh[tid] += t;
        __syncthreads();
    }
    if (tid < nb) bsum[tid] = sh[tid] - v;
}
__global__ void k_scan3() {
    int half = gridDim.x >> 1;
    bool isC = blockIdx.x < half;
    int* rowp = isC ? g_rowc : g_rowd;
    const int* bsum = isC ? g_bsumc : g_bsumd;
    int b = isC ? blockIdx.x : blockIdx.x - half;
    int g = b * SB + threadIdx.x;
    if (g < NN) rowp[g] += bsum[b];
}

// ---------------- fused CSR placement ----------------
__global__ void k_place(const void* __restrict__ eic, const void* __restrict__ eid, int gEC) {
    long long b = blockIdx.x;
    if (b < gEC) {
        int e = (int)(b * blockDim.x + threadIdx.x);
        if (e < EC) {
            int src, dst; load_edge(eic, EC, e, src, dst);
            g_csrc[g_rowc[dst] + atomicAdd(&g_curc[dst], 1)] = src;
        }
    } else {
        int e = (int)((b - gEC) * blockDim.x + threadIdx.x);
        if (e < ED) {
            int src, dst; load_edge(eid, ED, e, src, dst);
            g_csrd[g_rowd[dst] + atomicAdd(&g_curd[dst], 1)] = src;
        }
    }
}

// ---------------- z for layer 1: z = x @ W1l^T (fp16 out) ----------------
__global__ void k_z_first(const float* __restrict__ x, const float* __restrict__ W1l) {
    __shared__ float w[HH * FIN];
    if (threadIdx.x < HH * FIN) w[threadIdx.x] = W1l[threadIdx.x];
    __syncthreads();
    int i = blockIdx.x * blockDim.x + threadIdx.x;
    if (i >= NN) return;
    float xv[FIN];
#pragma unroll
    for (int f = 0; f < FIN; f++) xv[f] = x[i * FIN + f];
    float z[HH];
#pragma unroll
    for (int h = 0; h < HH; h++) {
        float s = 0.f;
#pragma unroll
        for (int f = 0; f < FIN; f++) s += xv[f] * w[h * FIN + f];
        z[h] = s;
    }
    __half2 out[4];
#pragma unroll
    for (int k = 0; k < 4; k++) out[k] = __floats2half2_rn(z[2 * k], z[2 * k + 1]);
    *(uint4*)&g_zh[i * HH] = *(uint4*)out;
}

// ---------------- warp-cooperative gather: lane-local acc over row ----------------
__device__ __forceinline__ void warp_gather(int s, int d, int lane,
                                            const int* __restrict__ csr, float acc[HH]) {
    int e = s + d;
    for (int p = s + lane; p < e; p += 32) {
        int idx = __ldg(&csr[p]);                       // coalesced: 32 lanes, 1-2 lines
        uint4 a = __ldg((const uint4*)&g_zh[idx * HH]); // random: 1 wavefront/lane (floor)
        const __half2* ah = (const __half2*)&a;
#pragma unroll
        for (int k = 0; k < 4; k++) {
            float2 fa = __half22float2(ah[k]);
            acc[2 * k]     += fa.x;
            acc[2 * k + 1] += fa.y;
        }
    }
}

// reduce acc[HH] to lane 0
__device__ __forceinline__ void warp_reduce(float acc[HH]) {
#pragma unroll
    for (int h = 0; h < HH; h++) {
#pragma unroll
        for (int o = 16; o; o >>= 1)
            acc[h] += __shfl_down_sync(FULLM, acc[h], o);
    }
}

// ---------------- software grid sync (GSYNC blocks, residency guaranteed) ----------
__device__ __forceinline__ void grid_sync(int layer) {
    __syncthreads();
    if (threadIdx.x == 0) {
        atomicAdd(&g_arrive[layer], 1u);
        while (*(volatile unsigned*)&g_arrive[layer] < gridDim.x) {}
        __threadfence();
    }
    __syncthreads();
}

__device__ __forceinline__ void bn_params(int layer, float* sbn, double* sd) {
    int tid = threadIdx.x;
    if (tid < 16) {
        double s = 0.0;
#pragma unroll
        for (int k = 0; k < NSLICE; k++) s += g_stats[layer][k][tid];
        sd[tid] = s;
    }
    __syncthreads();
    if (tid < 8) {
        double m = sd[tid] / (double)NN;
        double v = sd[8 + tid] / (double)NN - m * m;
        sbn[tid] = (float)m;
        sbn[8 + tid] = (float)rsqrt(v + BN_EPS);
    }
    __syncthreads();
}

// post-sync: BN apply + out write + optional next-z; coalesced thread-per-node loop
__device__ __forceinline__ void apply_phase(const float* sbn, const float* sg, const float* sb,
                                            const float* wl, float* __restrict__ outp,
                                            int writeZ) {
    int stride = gridDim.x * blockDim.x;
    for (int i = blockIdx.x * blockDim.x + threadIdx.x; i < NN; i += stride) {
        float4 y0 = *(const float4*)&g_y[i * HH];
        float4 y1 = *(const float4*)&g_y[i * HH + 4];
        float hv[HH] = {y0.x, y0.y, y0.z, y0.w, y1.x, y1.y, y1.z, y1.w};
#pragma unroll
        for (int h = 0; h < HH; h++)
            hv[h] = (hv[h] - sbn[h]) * sbn[8 + h] * sg[h] + sb[h];
        *(float4*)&outp[i * HH]     = make_float4(hv[0], hv[1], hv[2], hv[3]);
        *(float4*)&outp[i * HH + 4] = make_float4(hv[4], hv[5], hv[6], hv[7]);
        if (writeZ) {
            float z[HH];
#pragma unroll
            for (int h = 0; h < HH; h++) {
                float s = 0.f;
#pragma unroll
                for (int f = 0; f < HH; f++) s += hv[f] * wl[h * HH + f];
                z[h] = s;
            }
            __half2 zo[4];
#pragma unroll
            for (int k = 0; k < 4; k++) zo[k] = __floats2half2_rn(z[2 * k], z[2 * k + 1]);
            *(uint4*)&g_zh[i * HH] = *(uint4*)zo;
        }
    }
}

// lane0: finish node (mean + root matvec HH), norm+relu, write y, accumulate stats
__device__ __forceinline__ void finish_node_h(const float acc[HH], int node, int d,
                                              const float* w, float ss[HH], float sq[HH]) {
    float inv = 1.f / fmaxf((float)d, 1.f);
    float4 h0 = *(const float4*)&g_h[node * HH];
    float4 h1 = *(const float4*)&g_h[node * HH + 4];
    float hv[HH] = {h0.x, h0.y, h0.z, h0.w, h1.x, h1.y, h1.z, h1.w};
    float out[HH];
    float nrm = 0.f;
#pragma unroll
    for (int h = 0; h < HH; h++) {
        float sum = acc[h] * inv;
#pragma unroll
        for (int f = 0; f < HH; f++) sum += hv[f] * w[h * HH + f];
        out[h] = sum;
        nrm += sum * sum;
    }
    float invn = 1.f / fmaxf(sqrtf(nrm), L2_EPS);
#pragma unroll
    for (int h = 0; h < HH; h++) {
        float v = fmaxf(out[h] * invn, 0.f);
        out[h] = v;
        ss[h] += v;
        sq[h] += v * v;
    }
    *(float4*)&g_y[node * HH]     = make_float4(out[0], out[1], out[2], out[3]);
    *(float4*)&g_y[node * HH + 4] = make_float4(out[4], out[5], out[6], out[7]);
}

__device__ __forceinline__ void finish_node_x(const float acc[HH], int node, int d,
                                              const float* __restrict__ x, const float* w,
                                              float ss[HH], float sq[HH]) {
    float inv = 1.f / fmaxf((float)d, 1.f);
    float xv[FIN];
#pragma unroll
    for (int f = 0; f < FIN; f++) xv[f] = x[node * FIN + f];
    float out[HH];
    float nrm = 0.f;
#pragma unroll
    for (int h = 0; h < HH; h++) {
        float sum = acc[h] * inv;
#pragma unroll
        for (int f = 0; f < FIN; f++) sum += xv[f] * w[h * FIN + f];
        out[h] = sum;
        nrm += sum * sum;
    }
    float invn = 1.f / fmaxf(sqrtf(nrm), L2_EPS);
#pragma unroll
    for (int h = 0; h < HH; h++) {
        float v = fmaxf(out[h] * invn, 0.f);
        out[h] = v;
        ss[h] += v;
        sq[h] += v * v;
    }
    *(float4*)&g_y[node * HH]     = make_float4(out[0], out[1], out[2], out[3]);
    *(float4*)&g_y[node * HH + 4] = make_float4(out[4], out[5], out[6], out[7]);
}

// stats: lane0 register accumulators -> smem -> sliced global doubles
__device__ __forceinline__ void stats_commit(const float ss[HH], const float sq[HH],
                                             int lane, int layer, float* sstat) {
    if (lane == 0) {
#pragma unroll
        for (int h = 0; h < HH; h++) {
            atomicAdd(&sstat[h], ss[h]);
            atomicAdd(&sstat[8 + h], sq[h]);
        }
    }
    __syncthreads();
    if (threadIdx.x < 16) {
        atomicAdd(&g_stats[layer][blockIdx.x & (NSLICE - 1)][threadIdx.x], (double)sstat[threadIdx.x]);
        __threadfence();
    }
}

// ---------------- fused persistent layer 1 (root from x) ----------------
__global__ void __launch_bounds__(256, 2) k_layer_first(
    const float* __restrict__ x, const float* __restrict__ W1r,
    const float* __restrict__ gam, const float* __restrict__ bet,
    const float* __restrict__ Wlnext, float* __restrict__ outp)
{
    __shared__ float w[HH * FIN], wl[HH * HH], sstat[16], sg[HH], sb[HH], sbn[16];
    __shared__ double sd[16];
    int tid = threadIdx.x;
    if (tid < HH * FIN) w[tid] = W1r[tid];
    if (tid < HH * HH) wl[tid] = Wlnext[tid];
    if (tid < 16) sstat[tid] = 0.f;
    if (tid < HH) { sg[tid] = gam[tid]; sb[tid] = bet[tid]; }
    __syncthreads();
    int lane = tid & 31;
    int gwarp = (blockIdx.x * blockDim.x + tid) >> 5;
    int nwarp = (gridDim.x * blockDim.x) >> 5;
    float ss[HH], sq[HH];
#pragma unroll
    for (int h = 0; h < HH; h++) { ss[h] = 0.f; sq[h] = 0.f; }
    for (int node = gwarp; node < NN; node += nwarp) {
        int s = 0, d = 0;
        if (lane == 0) { s = g_rowc[node]; d = g_cntc[node]; }
        s = __shfl_sync(FULLM, s, 0);
        d = __shfl_sync(FULLM, d, 0);
        float acc[HH];
#pragma unroll
        for (int h = 0; h < HH; h++) acc[h] = 0.f;
        warp_gather(s, d, lane, g_csrc, acc);
        warp_reduce(acc);
        if (lane == 0) finish_node_x(acc, node, d, x, w, ss, sq);
    }
    stats_commit(ss, sq, lane, 0, sstat);
    grid_sync(0);
    bn_params(0, sbn, sd);
    apply_phase(sbn, sg, sb, wl, outp, 1);
}

// ---------------- fused persistent layers 2..5 (root from g_h) ----------------
__global__ void __launch_bounds__(256, 2) k_layer(
    const int* __restrict__ row, const int* __restrict__ cnt, const int* __restrict__ csr,
    const float* __restrict__ Wr, const float* __restrict__ gam, const float* __restrict__ bet,
    const float* __restrict__ Wlnext, float* __restrict__ outp, int layer, int writeZ)
{
    __shared__ float w[HH * HH], wl[HH * HH], sstat[16], sg[HH], sb[HH], sbn[16];
    __shared__ double sd[16];
    int tid = threadIdx.x;
    if (tid < HH * HH) w[tid] = Wr[tid];
    if (writeZ && tid < HH * HH) wl[tid] = Wlnext[tid];
    if (tid < 16) sstat[tid] = 0.f;
    if (tid < HH) { sg[tid] = gam[tid]; sb[tid] = bet[tid]; }
    __syncthreads();
    int lane = tid & 31;
    int gwarp = (blockIdx.x * blockDim.x + tid) >> 5;
    int nwarp = (gridDim.x * blockDim.x) >> 5;
    float ss[HH], sq[HH];
#pragma unroll
    for (int h = 0; h < HH; h++) { ss[h] = 0.f; sq[h] = 0.f; }
    for (int node = gwarp; node < NN; node += nwarp) {
        int s = 0, d = 0;
        if (lane == 0) { s = row[node]; d = cnt[node]; }
        s = __shfl_sync(FULLM, s, 0);
        d = __shfl_sync(FULLM, d, 0);
        float acc[HH];
#pragma unroll
        for (int h = 0; h < HH; h++) acc[h] = 0.f;
        warp_gather(s, d, lane, csr, acc);
        warp_reduce(acc);
        if (lane == 0) finish_node_h(acc, node, d, w, ss, sq);
    }
    stats_commit(ss, sq, lane, layer, sstat);
    grid_sync(layer);
    bn_params(layer, sbn, sd);
    apply_phase(sbn, sg, sb, wl, outp, writeZ);
}

// ---------------- host ----------------
extern "C" void kernel_launch(void* const* d_in, const int* in_sizes, int n_in,
                              void* d_out, int out_size) {
    const float* x   = (const float*)d_in[0];
    const void*  eic = d_in[1];
    const void*  eid = d_in[2];
    const float* W1l = (const float*)d_in[3];
    const float* W1r = (const float*)d_in[4];
    const float* W2l = (const float*)d_in[5];
    const float* W2r = (const float*)d_in[6];
    const float* W3l = (const float*)d_in[7];
    const float* W3r = (const float*)d_in[8];
    const float* W4l = (const float*)d_in[9];
    const float* W4r = (const float*)d_in[10];
    const float* g1 = (const float*)d_in[11]; const float* b1 = (const float*)d_in[12];
    const float* g2 = (const float*)d_in[13]; const float* b2 = (const float*)d_in[14];
    const float* g3 = (const float*)d_in[15]; const float* b3 = (const float*)d_in[16];
    const float* g4 = (const float*)d_in[17]; const float* b4 = (const float*)d_in[18];
    float* out = (float*)d_out;

    const int T = 256;
    const int gN  = (NN + T - 1) / T;
    const int gEC = (EC + T - 1) / T;
    const int gED = (ED + T - 1) / T;
    const int nbN = (NN + SB - 1) / SB;

    int* prc;   cudaGetSymbolAddress((void**)&prc, g_rowc);
    int* prd;   cudaGetSymbolAddress((void**)&prd, g_rowd);
    int* pcc;   cudaGetSymbolAddress((void**)&pcc, g_cntc);
    int* pcd;   cudaGetSymbolAddress((void**)&pcd, g_cntd);
    int* pcsrc; cudaGetSymbolAddress((void**)&pcsrc, g_csrc);
    int* pcsrd; cudaGetSymbolAddress((void**)&pcsrd, g_csrd);
    float* ph;  cudaGetSymbolAddress((void**)&ph, g_h);

    // ---- CSR build ----
    k_init<<<gN, T>>>();
    k_detect<<<1, 32>>>((const int*)eic);
    k_count<<<gEC + gED, T>>>(eic, eid, gEC);
    k_scan1<<<2 * nbN, SB>>>();
    k_scan2<<<2, 256>>>(nbN);
    k_scan3<<<2 * nbN, SB>>>();
    k_place<<<gEC + gED, T>>>(eic, eid, gEC);
    k_z_first<<<gN, T>>>(x, W1l);

    // ---- fused persistent layers (GSYNC blocks, residency-guaranteed grid sync) ----
    k_layer_first<<<GSYNC, T>>>(x, W1r, g1, b1, W4l, ph);
    k_layer<<<GSYNC, T>>>(prc, pcc, pcsrc, W4r, g2, b2, W2l, ph, 1, 1);
    k_layer<<<GSYNC, T>>>(prd, pcd, pcsrd, W2r, g3, b3, W3l, ph, 2, 1);
    k_layer<<<GSYNC, T>>>(prc, pcc, pcsrc, W3r, g4, b4, W3l, ph, 3, 1);
    k_layer<<<GSYNC, T>>>(prc, pcc, pcsrc, W3r, g4, b4, nullptr, out, 4, 0);
}

// round 13
// speedup vs baseline: 1.2143x; 1.2143x over previous
#include <cuda_runtime.h>
#include <cuda_fp16.h>

#define NN 100000
#define EC 6400000
#define ED 400000
#define HH 8
#define FIN 5
#define BN_EPS 1e-5
#define L2_EPS 1e-12f
#define SB 512
#define NSLICE 8
#define FULLM 0xffffffffu
#define TS 12500                    // src-tile size (nodes); 8 tiles cover 100K
#define NT 8
#define NPB 676                     // nodes per block: 148*676 >= NN
#define GEC 148
#define ECP (EC + 3 * NN * NT)      // per-segment pad-to-4 worst case
#define SMEMB (TS * 16)             // 200,000 B dynamic smem -> 1 block/SM guaranteed

// ---------------- scratch ----------------
__device__ __align__(16) int g_csrc[ECP];    // EC CSR, segment-bucketed by src tile
__device__ __align__(16) int g_csrd[ED];     // ED CSR (plain, R8 style)
__device__ int g_cnt2[NN * NT];              // per (dst, tile) counts
__device__ int g_segptr[NN * NT];            // segment starts (padded layout)
__device__ int g_segcur[NN * NT];            // placement cursors
__device__ int g_cntc[NN];                   // EC true degree
__device__ int g_cntd[NN];
__device__ int g_curd[NN];
__device__ int g_rowc[NN];
__device__ int g_rowd[NN];
__device__ int g_bsumc[256];
__device__ int g_bsumd[256];
__device__ __align__(16) __half g_zh[NN * HH];   // fp16 gather payload
__device__ __align__(16) float  g_h[NN * HH];    // post-BN features
__device__ __align__(16) float  g_y[NN * HH];    // pre-BN activations
__device__ double   g_stats[5][NSLICE][16];
__device__ unsigned g_arrive[5];
__device__ int      g_mode;

// ---------------- init ----------------
__global__ void k_init() {
    int i = blockIdx.x * blockDim.x + threadIdx.x;
    if (i < NN * NT) g_cnt2[i] = 0;
    if (i < NN) { g_cntd[i] = 0; g_curd[i] = 0; }
    if (i < 5 * NSLICE * 16) ((double*)g_stats)[i] = 0.0;
    if (i < 5) g_arrive[i] = 0u;
}

// ---------------- dtype detect ----------------
__global__ void k_detect(const int* __restrict__ ei) {
    int lane = threadIdx.x;
    int v = ei[2 * lane + 1];
    unsigned ball = __ballot_sync(FULLM, v == 0);
    if (lane == 0) g_mode = (ball == FULLM) ? 1 : 0;
}

__device__ __forceinline__ void load_edge(const void* ei, int E, int e, int& src, int& dst) {
    if (g_mode) {
        const long long* p = (const long long*)ei;
        src = (int)p[e]; dst = (int)p[E + e];
    } else {
        const int* p = (const int*)ei;
        src = p[e]; dst = p[E + e];
    }
}

// ---------------- fused count: EC -> cnt2[dst][tile], ED -> cntd ----------------
__global__ void k_count(const void* __restrict__ eic, const void* __restrict__ eid, int gEC) {
    long long b = blockIdx.x;
    if (b < gEC) {
        int e = (int)(b * blockDim.x + threadIdx.x);
        if (e < EC) {
            int src, dst; load_edge(eic, EC, e, src, dst);
            atomicAdd(&g_cnt2[dst * NT + src / TS], 1);
        }
    } else {
        int e = (int)((b - gEC) * blockDim.x + threadIdx.x);
        if (e < ED) {
            int src, dst; load_edge(eid, ED, e, src, dst);
            atomicAdd(&g_cntd[dst], 1);
        }
    }
}

// ---------------- fused scans: EC rows = sum of padded segments; ED plain --------
__global__ void k_scan1() {
    __shared__ int sh[SB];
    int half = gridDim.x >> 1;
    bool isC = blockIdx.x < half;
    int* rowp = isC ? g_rowc : g_rowd;
    int* bsum = isC ? g_bsumc : g_bsumd;
    int b = isC ? blockIdx.x : blockIdx.x - half;
    int tid = threadIdx.x;
    int g = b * SB + tid;
    int v = 0;
    if (g < NN) {
        if (isC) {
#pragma unroll
            for (int t = 0; t < NT; t++) v += (g_cnt2[g * NT + t] + 3) & ~3;
        } else v = g_cntd[g];
    }
    sh[tid] = v; __syncthreads();
#pragma unroll
    for (int o = 1; o < SB; o <<= 1) {
        int t = (tid >= o) ? sh[tid - o] : 0;
        __syncthreads();
        sh[tid] += t;
        __syncthreads();
    }
    if (g < NN) rowp[g] = sh[tid] - v;
    if (tid == SB - 1) bsum[b] = sh[SB - 1];
}
__global__ void k_scan2(int nb) {
    __shared__ int sh[256];
    int* bsum = (blockIdx.x == 0) ? g_bsumc : g_bsumd;
    int tid = threadIdx.x;
    int v = (tid < nb) ? bsum[tid] : 0;
    sh[tid] = v; __syncthreads();
#pragma unroll
    for (int o = 1; o < 256; o <<= 1) {
        int t = (tid >= o) ? sh[tid - o] : 0;
        __syncthreads();
        sh[tid] += t;
        __syncthreads();
    }
    if (tid < nb) bsum[tid] = sh[tid] - v;
}
__global__ void k_scan3() {
    int half = gridDim.x >> 1;
    bool isC = blockIdx.x < half;
    int* rowp = isC ? g_rowc : g_rowd;
    const int* bsum = isC ? g_bsumc : g_bsumd;
    int b = isC ? blockIdx.x : blockIdx.x - half;
    int g = b * SB + threadIdx.x;
    if (g < NN) rowp[g] += bsum[b];
}

// ---------------- EC segment starts + true degree ----------------
__global__ void k_segstart() {
    int i = blockIdx.x * blockDim.x + threadIdx.x;
    if (i >= NN) return;
    int base = g_rowc[i];
    int run = 0, tot = 0;
#pragma unroll
    for (int t = 0; t < NT; t++) {
        int sidx = i * NT + t;
        int len = g_cnt2[sidx];
        g_segptr[sidx] = base + run;
        g_segcur[sidx] = base + run;
        run += (len + 3) & ~3;
        tot += len;
    }
    g_cntc[i] = tot;
}

// ---------------- fused placement ----------------
__global__ void k_place(const void* __restrict__ eic, const void* __restrict__ eid, int gEC) {
    long long b = blockIdx.x;
    if (b < gEC) {
        int e = (int)(b * blockDim.x + threadIdx.x);
        if (e < EC) {
            int src, dst; load_edge(eic, EC, e, src, dst);
            int pos = atomicAdd(&g_segcur[dst * NT + src / TS], 1);
            g_csrc[pos] = src;
        }
    } else {
        int e = (int)((b - gEC) * blockDim.x + threadIdx.x);
        if (e < ED) {
            int src, dst; load_edge(eid, ED, e, src, dst);
            g_csrd[g_rowd[dst] + atomicAdd(&g_curd[dst], 1)] = src;
        }
    }
}

// ---------------- fill EC segment pads with -1 ----------------
__global__ void k_fillc() {
    int i = blockIdx.x * blockDim.x + threadIdx.x;
    if (i >= NN * NT) return;
    int start = g_segptr[i], len = g_cnt2[i];
    int pad = (len + 3) & ~3;
    for (int j = len; j < pad; j++) g_csrc[start + j] = -1;
}

// ---------------- z for layer 1 ----------------
__global__ void k_z_first(const float* __restrict__ x, const float* __restrict__ W1l) {
    __shared__ float w[HH * FIN];
    if (threadIdx.x < HH * FIN) w[threadIdx.x] = W1l[threadIdx.x];
    __syncthreads();
    int i = blockIdx.x * blockDim.x + threadIdx.x;
    if (i >= NN) return;
    float xv[FIN];
#pragma unroll
    for (int f = 0; f < FIN; f++) xv[f] = x[i * FIN + f];
    float z[HH];
#pragma unroll
    for (int h = 0; h < HH; h++) {
        float s = 0.f;
#pragma unroll
        for (int f = 0; f < FIN; f++) s += xv[f] * w[h * FIN + f];
        z[h] = s;
    }
    __half2 out[4];
#pragma unroll
    for (int k = 0; k < 4; k++) out[k] = __floats2half2_rn(z[2 * k], z[2 * k + 1]);
    *(uint4*)&g_zh[i * HH] = *(uint4*)out;
}

// ---------------- shared helpers ----------------
__device__ __forceinline__ void addp(const uint4& a, float acc[HH]) {
    const __half2* ah = (const __half2*)&a;
#pragma unroll
    for (int k = 0; k < 4; k++) {
        float2 fa = __half22float2(ah[k]);
        acc[2 * k]     += fa.x;
        acc[2 * k + 1] += fa.y;
    }
}

__device__ __forceinline__ void grid_sync(int layer) {
    __syncthreads();
    if (threadIdx.x == 0) {
        atomicAdd(&g_arrive[layer], 1u);
        while (*(volatile unsigned*)&g_arrive[layer] < gridDim.x) {}
        __threadfence();
    }
    __syncthreads();
}

__device__ __forceinline__ void bn_params(int layer, float* sbn, double* sd) {
    int tid = threadIdx.x;
    if (tid < 16) {
        double s = 0.0;
#pragma unroll
        for (int k = 0; k < NSLICE; k++) s += g_stats[layer][k][tid];
        sd[tid] = s;
    }
    __syncthreads();
    if (tid < 8) {
        double m = sd[tid] / (double)NN;
        double v = sd[8 + tid] / (double)NN - m * m;
        sbn[tid] = (float)m;
        sbn[8 + tid] = (float)rsqrt(v + BN_EPS);
    }
    __syncthreads();
}

__device__ __forceinline__ void apply_phase(const float* sbn, const float* sg, const float* sb,
                                            const float* wl, float* __restrict__ outp,
                                            int writeZ) {
    int stride = gridDim.x * blockDim.x;
    for (int i = blockIdx.x * blockDim.x + threadIdx.x; i < NN; i += stride) {
        float4 y0 = *(const float4*)&g_y[i * HH];
        float4 y1 = *(const float4*)&g_y[i * HH + 4];
        float hv[HH] = {y0.x, y0.y, y0.z, y0.w, y1.x, y1.y, y1.z, y1.w};
#pragma unroll
        for (int h = 0; h < HH; h++)
            hv[h] = (hv[h] - sbn[h]) * sbn[8 + h] * sg[h] + sb[h];
        *(float4*)&outp[i * HH]     = make_float4(hv[0], hv[1], hv[2], hv[3]);
        *(float4*)&outp[i * HH + 4] = make_float4(hv[4], hv[5], hv[6], hv[7]);
        if (writeZ) {
            float z[HH];
#pragma unroll
            for (int h = 0; h < HH; h++) {
                float s = 0.f;
#pragma unroll
                for (int f = 0; f < HH; f++) s += hv[f] * wl[h * HH + f];
                z[h] = s;
            }
            __half2 zo[4];
#pragma unroll
            for (int k = 0; k < 4; k++) zo[k] = __floats2half2_rn(z[2 * k], z[2 * k + 1]);
            *(uint4*)&g_zh[i * HH] = *(uint4*)zo;
        }
    }
}

// norm+relu+write y, accumulating per-thread stats
__device__ __forceinline__ void tail_node(float out[HH], int node, float ss[HH], float sq[HH]) {
    float nrm = 0.f;
#pragma unroll
    for (int h = 0; h < HH; h++) nrm += out[h] * out[h];
    float invn = 1.f / fmaxf(sqrtf(nrm), L2_EPS);
#pragma unroll
    for (int h = 0; h < HH; h++) {
        float v = fmaxf(out[h] * invn, 0.f);
        out[h] = v;
        ss[h] += v;
        sq[h] += v * v;
    }
    *(float4*)&g_y[node * HH]     = make_float4(out[0], out[1], out[2], out[3]);
    *(float4*)&g_y[node * HH + 4] = make_float4(out[4], out[5], out[6], out[7]);
}

// per-thread stats -> warp -> smem -> sliced global
__device__ __forceinline__ void stats_commit(const float ss[HH], const float sq[HH],
                                             int layer, float* sstat) {
#pragma unroll
    for (int h = 0; h < HH; h++) {
        float s = ss[h], q = sq[h];
#pragma unroll
        for (int o = 16; o; o >>= 1) {
            s += __shfl_down_sync(FULLM, s, o);
            q += __shfl_down_sync(FULLM, q, o);
        }
        if ((threadIdx.x & 31) == 0) {
            atomicAdd(&sstat[h], s);
            atomicAdd(&sstat[8 + h], q);
        }
    }
    __syncthreads();
    if (threadIdx.x < 16) {
        atomicAdd(&g_stats[layer][blockIdx.x & (NSLICE - 1)][threadIdx.x],
                  (double)sstat[threadIdx.x]);
        __threadfence();
    }
}

// ---------------- EC tiled-smem layer (148 blocks x 512 thr; 1/SM guaranteed) -----
__device__ __forceinline__ void process_seg(int node, int t, const uint4* tile, float acc[HH]) {
    int sidx = node * NT + t;
    int p = g_segptr[sidx];
    int len = g_cnt2[sidx];
    int nchunk = (len + 3) >> 2;
    const int4* ip = (const int4*)&g_csrc[p];   // 16B-aligned by construction
    int base = t * TS;
    for (int c = 0; c < nchunk; c++) {
        int4 id = __ldg(ip + c);
        if (id.x >= 0) addp(tile[id.x - base], acc);
        if (id.y >= 0) addp(tile[id.y - base], acc);
        if (id.z >= 0) addp(tile[id.z - base], acc);
        if (id.w >= 0) addp(tile[id.w - base], acc);
    }
}

__device__ __forceinline__ void finish_ec(float acc[HH], int node,
                                          const float* __restrict__ rootF, int FDIM,
                                          const float* w, float ss[HH], float sq[HH]) {
    int d = g_cntc[node];
    float inv = 1.f / fmaxf((float)d, 1.f);
    float out[HH];
    if (FDIM == HH) {
        float4 h0 = *(const float4*)&rootF[node * HH];
        float4 h1 = *(const float4*)&rootF[node * HH + 4];
        float rv[HH] = {h0.x, h0.y, h0.z, h0.w, h1.x, h1.y, h1.z, h1.w};
#pragma unroll
        for (int h = 0; h < HH; h++) {
            float sum = acc[h] * inv;
#pragma unroll
            for (int f = 0; f < HH; f++) sum += rv[f] * w[h * HH + f];
            out[h] = sum;
        }
    } else {
        float rv[FIN];
#pragma unroll
        for (int f = 0; f < FIN; f++) rv[f] = rootF[node * FIN + f];
#pragma unroll
        for (int h = 0; h < HH; h++) {
            float sum = acc[h] * inv;
#pragma unroll
            for (int f = 0; f < FIN; f++) sum += rv[f] * w[h * FIN + f];
            out[h] = sum;
        }
    }
    tail_node(out, node, ss, sq);
}

__global__ void __launch_bounds__(512, 1) k_layer_ec(
    const float* __restrict__ rootF, int FDIM, const float* __restrict__ Wr,
    const float* __restrict__ gam, const float* __restrict__ bet,
    const float* __restrict__ Wlnext, float* __restrict__ outp, int layer, int writeZ)
{
    extern __shared__ __align__(16) unsigned char smraw[];
    uint4* tile = (uint4*)smraw;
    __shared__ float w[HH * HH], wl[HH * HH], sstat[16], sg[HH], sb[HH], sbn[16];
    __shared__ double sd[16];
    int tid = threadIdx.x;
    if (tid < HH * FDIM) w[tid] = Wr[tid];
    if (writeZ && tid < HH * HH) wl[tid] = Wlnext[tid];
    if (tid < 16) sstat[tid] = 0.f;
    if (tid < HH) { sg[tid] = gam[tid]; sb[tid] = bet[tid]; }
    __syncthreads();

    int n0 = blockIdx.x * NPB;
    int nEnd = min(n0 + NPB, NN);
    int nodeA = n0 + tid;
    int nodeB = n0 + 512 + tid;
    bool vA = nodeA < nEnd, vB = nodeB < nEnd;
    float acc0[HH], acc1[HH];
#pragma unroll
    for (int h = 0; h < HH; h++) { acc0[h] = 0.f; acc1[h] = 0.f; }

    for (int t = 0; t < NT; t++) {
        for (int j = tid; j < TS; j += 512)
            tile[j] = *(const uint4*)&g_zh[(t * TS + j) * HH];
        __syncthreads();
        if (vA) process_seg(nodeA, t, tile, acc0);
        if (vB) process_seg(nodeB, t, tile, acc1);
        __syncthreads();
    }

    float ss[HH], sq[HH];
#pragma unroll
    for (int h = 0; h < HH; h++) { ss[h] = 0.f; sq[h] = 0.f; }
    if (vA) finish_ec(acc0, nodeA, rootF, FDIM, w, ss, sq);
    if (vB) finish_ec(acc1, nodeB, rootF, FDIM, w, ss, sq);
    stats_commit(ss, sq, layer, sstat);
    grid_sync(layer);
    bn_params(layer, sbn, sd);
    apply_phase(sbn, sg, sb, wl, outp, writeZ);
}

// ---------------- ED layer: R8-proven gather, NO grid sync (split kernels) --------
__device__ __forceinline__ void gather_row(int s, int d, const int* __restrict__ csr,
                                           float acc[HH]) {
    int e = s + d;
    int p = s;
    for (; p + 3 < e; p += 4) {
        int s0 = __ldg(&csr[p]);
        int s1 = __ldg(&csr[p + 1]);
        int s2 = __ldg(&csr[p + 2]);
        int s3 = __ldg(&csr[p + 3]);
        uint4 a0 = __ldg((const uint4*)&g_zh[s0 * HH]);
        uint4 a1 = __ldg((const uint4*)&g_zh[s1 * HH]);
        uint4 a2 = __ldg((const uint4*)&g_zh[s2 * HH]);
        uint4 a3 = __ldg((const uint4*)&g_zh[s3 * HH]);
        addp(a0, acc); addp(a1, acc); addp(a2, acc); addp(a3, acc);
    }
    for (; p < e; p++) {
        int s0 = __ldg(&csr[p]);
        uint4 a0 = __ldg((const uint4*)&g_zh[s0 * HH]);
        addp(a0, acc);
    }
}

__global__ void __launch_bounds__(256) k_layer_ed(const float* __restrict__ Wr, int layer) {
    __shared__ float w[HH * HH], sstat[16];
    int tid = threadIdx.x;
    if (tid < HH * HH) w[tid] = Wr[tid];
    if (tid < 16) sstat[tid] = 0.f;
    __syncthreads();
    int i = blockIdx.x * blockDim.x + tid;
    float ss[HH], sq[HH];
#pragma unroll
    for (int h = 0; h < HH; h++) { ss[h] = 0.f; sq[h] = 0.f; }
    if (i < NN) {
        int s = g_rowd[i], d = g_cntd[i];
        float acc[HH];
#pragma unroll
        for (int h = 0; h < HH; h++) acc[h] = 0.f;
        gather_row(s, d, g_csrd, acc);
        float inv = 1.f / fmaxf((float)d, 1.f);
        float4 h0 = *(const float4*)&g_h[i * HH];
        float4 h1 = *(const float4*)&g_h[i * HH + 4];
        float hv[HH] = {h0.x, h0.y, h0.z, h0.w, h1.x, h1.y, h1.z, h1.w};
        float out[HH];
#pragma unroll
        for (int h = 0; h < HH; h++) {
            float sum = acc[h] * inv;
#pragma unroll
            for (int f = 0; f < HH; f++) sum += hv[f] * w[h * HH + f];
            out[h] = sum;
        }
        tail_node(out, i, ss, sq);
    }
    stats_commit(ss, sq, layer, sstat);
}

__global__ void __launch_bounds__(256) k_bn_ed(
    int layer, const float* __restrict__ gam, const float* __restrict__ bet,
    const float* __restrict__ Wlnext, float* __restrict__ outp, int writeZ)
{
    __shared__ float wl[HH * HH], sg[HH], sb[HH], sbn[16];
    __shared__ double sd[16];
    int tid = threadIdx.x;
    if (writeZ && tid < HH * HH) wl[tid] = Wlnext[tid];
    if (tid < HH) { sg[tid] = gam[tid]; sb[tid] = bet[tid]; }
    __syncthreads();
    bn_params(layer, sbn, sd);
    apply_phase(sbn, sg, sb, wl, outp, writeZ);
}

// ---------------- host ----------------
extern "C" void kernel_launch(void* const* d_in, const int* in_sizes, int n_in,
                              void* d_out, int out_size) {
    const float* x   = (const float*)d_in[0];
    const void*  eic = d_in[1];
    const void*  eid = d_in[2];
    const float* W1l = (const float*)d_in[3];
    const float* W1r = (const float*)d_in[4];
    const float* W2l = (const float*)d_in[5];
    const float* W2r = (const float*)d_in[6];
    const float* W3l = (const float*)d_in[7];
    const float* W3r = (const float*)d_in[8];
    const float* W4l = (const float*)d_in[9];
    const float* W4r = (const float*)d_in[10];
    const float* g1 = (const float*)d_in[11]; const float* b1 = (const float*)d_in[12];
    const float* g2 = (const float*)d_in[13]; const float* b2 = (const float*)d_in[14];
    const float* g3 = (const float*)d_in[15]; const float* b3 = (const float*)d_in[16];
    const float* g4 = (const float*)d_in[17]; const float* b4 = (const float*)d_in[18];
    float* out = (float*)d_out;

    const int T = 256;
    const int gN   = (NN + T - 1) / T;
    const int gN8  = (NN * NT + T - 1) / T;
    const int gEC  = (EC + T - 1) / T;
    const int gED  = (ED + T - 1) / T;
    const int nbN  = (NN + SB - 1) / SB;

    static int smem_set = 0;
    if (!smem_set) {
        cudaFuncSetAttribute(k_layer_ec, cudaFuncAttributeMaxDynamicSharedMemorySize, SMEMB);
        smem_set = 1;
    }

    float* ph;  cudaGetSymbolAddress((void**)&ph, g_h);

    // ---- build ----
    k_init<<<gN8, T>>>();
    k_detect<<<1, 32>>>((const int*)eic);
    k_count<<<gEC + gED, T>>>(eic, eid, gEC);
    k_scan1<<<2 * nbN, SB>>>();
    k_scan2<<<2, 256>>>(nbN);
    k_scan3<<<2 * nbN, SB>>>();
    k_segstart<<<gN, T>>>();
    k_place<<<gEC + gED, T>>>(eic, eid, gEC);
    k_fillc<<<gN8, T>>>();
    k_z_first<<<gN, T>>>(x, W1l);

    // ---- layers ----
    // layer 1 (EC): conv1 + bn1, next payload W4l
    k_layer_ec<<<GEC, 512, SMEMB>>>(x, FIN, W1r, g1, b1, W4l, ph, 0, 1);
    // layer 2 (EC): conv4 + bn2, next W2l
    k_layer_ec<<<GEC, 512, SMEMB>>>(ph, HH, W4r, g2, b2, W2l, ph, 1, 1);
    // layer 3 (ED): conv2 + bn3, next W3l — split kernels, no grid sync
    k_layer_ed<<<gN, T>>>(W2r, 2);
    k_bn_ed<<<gN, T>>>(2, g3, b3, W3l, ph, 1);
    // layer 4 (EC): conv3 + bn4, next W3l
    k_layer_ec<<<GEC, 512, SMEMB>>>(ph, HH, W3r, g4, b4, W3l, ph, 3, 1);
    // layer 5 (EC): conv3 + bn4 -> d_out
    k_layer_ec<<<GEC, 512, SMEMB>>>(ph, HH, W3r, g4, b4, nullptr, out, 4, 0);
}

// round 14
// speedup vs baseline: 1.6801x; 1.3836x over previous
#include <cuda_runtime.h>
#include <cuda_fp16.h>

#define NN 100000
#define EC 6400000
#define ED 400000
#define HH 8
#define FIN 5
#define BN_EPS 1e-5
#define L2_EPS 1e-12f
#define SB 512
#define NSLICE 8
#define FULLM 0xffffffffu
// padded CSR capacity: every row rounded up to multiple of 4
#define ECP (EC + 4 * NN)
#define EDP (ED + 4 * NN)

// ---------------- scratch ----------------
__device__ __align__(16) int g_csrc[ECP];    // padded CSR src lists (by dst)
__device__ __align__(16) int g_csrd[EDP];
__device__ int   g_cntc[NN];                 // true degrees
__device__ int   g_cntd[NN];
__device__ int   g_curc[NN];
__device__ int   g_curd[NN];
__device__ int   g_rowc[NN];                 // padded, 4-aligned row starts
__device__ int   g_rowd[NN];
__device__ int   g_bsumc[256];
__device__ int   g_bsumd[256];
__device__ __align__(16) __half g_zh[(NN + 1) * HH]; // fp16 payload; slot NN = zero sentinel
__device__ __align__(16) float  g_h[NN * HH];        // post-BN features
__device__ double   g_stats[5][NSLICE][16];
__device__ unsigned g_arrive[5];
__device__ int      g_mode;

// ---------------- init ----------------
__global__ void k_init() {
    int i = blockIdx.x * blockDim.x + threadIdx.x;
    if (i < NN) { g_cntc[i] = 0; g_cntd[i] = 0; g_curc[i] = 0; g_curd[i] = 0; }
    if (i < 5 * NSLICE * 16) ((double*)g_stats)[i] = 0.0;
    if (i < 5) g_arrive[i] = 0u;
    if (i < HH) g_zh[NN * HH + i] = __float2half(0.f);   // zero sentinel payload
}

// ---------------- int64 vs int32 edge dtype detection ----------------
__global__ void k_detect(const int* __restrict__ ei) {
    int lane = threadIdx.x;
    int v = ei[2 * lane + 1];
    unsigned ball = __ballot_sync(FULLM, v == 0);
    if (lane == 0) g_mode = (ball == FULLM) ? 1 : 0;
}

__device__ __forceinline__ void load_edge(const void* ei, int E, int e, int& src, int& dst) {
    if (g_mode) {
        const long long* p = (const long long*)ei;
        src = (int)p[e]; dst = (int)p[E + e];
    } else {
        const int* p = (const int*)ei;
        src = p[e]; dst = p[E + e];
    }
}

// ---------------- fused count over both edge sets ----------------
__global__ void k_count(const void* __restrict__ eic, const void* __restrict__ eid, int gEC) {
    long long b = blockIdx.x;
    if (b < gEC) {
        int e = (int)(b * blockDim.x + threadIdx.x);
        if (e < EC) {
            int src, dst; load_edge(eic, EC, e, src, dst);
            atomicAdd(&g_cntc[dst], 1);
        }
    } else {
        int e = (int)((b - gEC) * blockDim.x + threadIdx.x);
        if (e < ED) {
            int src, dst; load_edge(eid, ED, e, src, dst);
            atomicAdd(&g_cntd[dst], 1);
        }
    }
}

// ---------------- fused scans over PADDED counts ----------------
__global__ void k_scan1() {
    __shared__ int sh[SB];
    int half = gridDim.x >> 1;
    bool isC = blockIdx.x < half;
    const int* cnt = isC ? g_cntc : g_cntd;
    int* rowp = isC ? g_rowc : g_rowd;
    int* bsum = isC ? g_bsumc : g_bsumd;
    int b = isC ? blockIdx.x : blockIdx.x - half;
    int tid = threadIdx.x;
    int g = b * SB + tid;
    int v = (g < NN) ? ((cnt[g] + 3) & ~3) : 0;     // pad row to multiple of 4
    sh[tid] = v; __syncthreads();
#pragma unroll
    for (int o = 1; o < SB; o <<= 1) {
        int t = (tid >= o) ? sh[tid - o] : 0;
        __syncthreads();
        sh[tid] += t;
        __syncthreads();
    }
    if (g < NN) rowp[g] = sh[tid] - v;
    if (tid == SB - 1) bsum[b] = sh[SB - 1];
}
__global__ void k_scan2(int nb) {
    __shared__ int sh[256];
    int* bsum = (blockIdx.x == 0) ? g_bsumc : g_bsumd;
    int tid = threadIdx.x;
    int v = (tid < nb) ? bsum[tid] : 0;
    sh[tid] = v; __syncthreads();
#pragma unroll
    for (int o = 1; o < 256; o <<= 1) {
        int t = (tid >= o) ? sh[tid - o] : 0;
        __syncthreads();
        sh[tid] += t;
        __syncthreads();
    }
    if (tid < nb) bsum[tid] = sh[tid] - v;
}
__global__ void k_scan3() {
    int half = gridDim.x >> 1;
    bool isC = blockIdx.x < half;
    int* rowp = isC ? g_rowc : g_rowd;
    const int* bsum = isC ? g_bsumc : g_bsumd;
    int b = isC ? blockIdx.x : blockIdx.x - half;
    int g = b * SB + threadIdx.x;
    if (g < NN) rowp[g] += bsum[b];
}

// ---------------- fused CSR placement (cursor-based) ----------------
__global__ void k_place(const void* __restrict__ eic, const void* __restrict__ eid, int gEC) {
    long long b = blockIdx.x;
    if (b < gEC) {
        int e = (int)(b * blockDim.x + threadIdx.x);
        if (e < EC) {
            int src, dst; load_edge(eic, EC, e, src, dst);
            g_csrc[g_rowc[dst] + atomicAdd(&g_curc[dst], 1)] = src;
        }
    } else {
        int e = (int)((b - gEC) * blockDim.x + threadIdx.x);
        if (e < ED) {
            int src, dst; load_edge(eid, ED, e, src, dst);
            g_csrd[g_rowd[dst] + atomicAdd(&g_curd[dst], 1)] = src;
        }
    }
}

// ---------------- fill padding slots with zero-sentinel (both CSRs) ----------------
__global__ void k_fill(int gN) {
    int b = blockIdx.x;
    bool isC = b < gN;
    int i = (isC ? b : b - gN) * blockDim.x + threadIdx.x;
    if (i >= NN) return;
    const int* cnt = isC ? g_cntc : g_cntd;
    const int* rowp = isC ? g_rowc : g_rowd;
    int* csr = isC ? g_csrc : g_csrd;
    int d = cnt[i];
    int pad = (d + 3) & ~3;
    int s = rowp[i];
    for (int j = d; j < pad; j++) csr[s + j] = NN;
}

// ---------------- z for layer 1: z = x @ W1l^T (fp16 out) ----------------
__global__ void k_z_first(const float* __restrict__ x, const float* __restrict__ W1l) {
    __shared__ float w[HH * FIN];
    if (threadIdx.x < HH * FIN) w[threadIdx.x] = W1l[threadIdx.x];
    __syncthreads();
    int i = blockIdx.x * blockDim.x + threadIdx.x;
    if (i >= NN) return;
    float xv[FIN];
#pragma unroll
    for (int f = 0; f < FIN; f++) xv[f] = x[i * FIN + f];
    float z[HH];
#pragma unroll
    for (int h = 0; h < HH; h++) {
        float s = 0.f;
#pragma unroll
        for (int f = 0; f < FIN; f++) s += xv[f] * w[h * FIN + f];
        z[h] = s;
    }
    __half2 out[4];
#pragma unroll
    for (int k = 0; k < 4; k++) out[k] = __floats2half2_rn(z[2 * k], z[2 * k + 1]);
    *(uint4*)&g_zh[i * HH] = *(uint4*)out;
}

// ---------------- gather helpers ----------------
__device__ __forceinline__ void acc_payload(const uint4& a, float acc[HH]) {
    const __half2* ah = (const __half2*)&a;
#pragma unroll
    for (int k = 0; k < 4; k++) {
        float2 fa = __half22float2(ah[k]);
        acc[2 * k]     += fa.x;
        acc[2 * k + 1] += fa.y;
    }
}

// padded row: pure int4 index loads, no epilogue branches (R7-proven)
__device__ __forceinline__ void gather_row(int s, int d, const int* __restrict__ csr,
                                           float acc[HH]) {
    int n4 = (d + 3) >> 2;
    const int4* ip = (const int4*)(csr + s);   // s is 4-aligned by construction
    for (int t = 0; t < n4; t++) {
        int4 id = __ldg(ip + t);
        uint4 a0 = __ldg((const uint4*)&g_zh[id.x * HH]);
        uint4 a1 = __ldg((const uint4*)&g_zh[id.y * HH]);
        uint4 a2 = __ldg((const uint4*)&g_zh[id.z * HH]);
        uint4 a3 = __ldg((const uint4*)&g_zh[id.w * HH]);
        acc_payload(a0, acc);
        acc_payload(a1, acc);
        acc_payload(a2, acc);
        acc_payload(a3, acc);
    }
}

// ---------------- block stats -> sliced global doubles (R8-proven) ----------------
__device__ __forceinline__ void stats_block(const float out[HH], int layer, float* sstat) {
    int tid = threadIdx.x;
#pragma unroll
    for (int h = 0; h < HH; h++) {
        float s = out[h];
        float q = out[h] * out[h];
#pragma unroll
        for (int o = 16; o; o >>= 1) {
            s += __shfl_down_sync(FULLM, s, o);
            q += __shfl_down_sync(FULLM, q, o);
        }
        if ((tid & 31) == 0) {
            atomicAdd(&sstat[h], s);
            atomicAdd(&sstat[8 + h], q);
        }
    }
    __syncthreads();
    if (tid < 16) {
        atomicAdd(&g_stats[layer][blockIdx.x & (NSLICE - 1)][tid], (double)sstat[tid]);
        __threadfence();
    }
}

// ---------------- software grid sync (391 blocks; 3/SM forced by launch bounds) ----
__device__ __forceinline__ void grid_sync(int layer) {
    __syncthreads();
    if (threadIdx.x == 0) {
        atomicAdd(&g_arrive[layer], 1u);
        while (*(volatile unsigned*)&g_arrive[layer] < gridDim.x) {}
        __threadfence();
    }
    __syncthreads();
}

__device__ __forceinline__ void bn_params(int layer, float* sbn, double* sd) {
    int tid = threadIdx.x;
    if (tid < 16) {
        double s = 0.0;
#pragma unroll
        for (int k = 0; k < NSLICE; k++) s += g_stats[layer][k][tid];
        sd[tid] = s;
    }
    __syncthreads();
    if (tid < 8) {
        double m = sd[tid] / (double)NN;
        double v = sd[8 + tid] / (double)NN - m * m;
        sbn[tid] = (float)m;
        sbn[8 + tid] = (float)rsqrt(v + BN_EPS);
    }
    __syncthreads();
}

// l2-normalize + relu in registers
__device__ __forceinline__ void norm_relu(float out[HH]) {
    float nrm = 0.f;
#pragma unroll
    for (int h = 0; h < HH; h++) nrm += out[h] * out[h];
    float invn = 1.f / fmaxf(sqrtf(nrm), L2_EPS);
#pragma unroll
    for (int h = 0; h < HH; h++) out[h] = fmaxf(out[h] * invn, 0.f);
}

// BN-apply + write outp + optional next-z, all from registers
__device__ __forceinline__ void apply_tail(const float out[HH], int i, const float* sbn,
                                           const float* sg, const float* sb, const float* wl,
                                           float* __restrict__ outp, int writeZ) {
    float hv[HH];
#pragma unroll
    for (int h = 0; h < HH; h++)
        hv[h] = (out[h] - sbn[h]) * sbn[8 + h] * sg[h] + sb[h];
    *(float4*)&outp[i * HH]     = make_float4(hv[0], hv[1], hv[2], hv[3]);
    *(float4*)&outp[i * HH + 4] = make_float4(hv[4], hv[5], hv[6], hv[7]);
    if (writeZ) {
        float z[HH];
#pragma unroll
        for (int h = 0; h < HH; h++) {
            float s = 0.f;
#pragma unroll
            for (int f = 0; f < HH; f++) s += hv[f] * wl[h * HH + f];
            z[h] = s;
        }
        __half2 zo[4];
#pragma unroll
        for (int k = 0; k < 4; k++) zo[k] = __floats2half2_rn(z[2 * k], z[2 * k + 1]);
        *(uint4*)&g_zh[i * HH] = *(uint4*)zo;
    }
}

// ---------------- fused layer 1 (root from x, F=5) ----------------
__global__ void __launch_bounds__(256, 3) k_layer_first(
    const float* __restrict__ x, const float* __restrict__ W1r,
    const float* __restrict__ gam, const float* __restrict__ bet,
    const float* __restrict__ Wlnext, float* __restrict__ outp)
{
    __shared__ float w[HH * FIN], wl[HH * HH], sstat[16], sg[HH], sb[HH], sbn[16];
    __shared__ double sd[16];
    int tid = threadIdx.x;
    if (tid < HH * FIN) w[tid] = W1r[tid];
    if (tid < HH * HH) wl[tid] = Wlnext[tid];
    if (tid < 16) sstat[tid] = 0.f;
    if (tid < HH) { sg[tid] = gam[tid]; sb[tid] = bet[tid]; }
    __syncthreads();
    int i = blockIdx.x * blockDim.x + tid;
    bool act = i < NN;
    float out[HH];
#pragma unroll
    for (int h = 0; h < HH; h++) out[h] = 0.f;
    if (act) {
        int s = g_rowc[i], d = g_cntc[i];
        float acc[HH];
#pragma unroll
        for (int h = 0; h < HH; h++) acc[h] = 0.f;
        gather_row(s, d, g_csrc, acc);
        float inv = 1.f / fmaxf((float)d, 1.f);
        float xv[FIN];
#pragma unroll
        for (int f = 0; f < FIN; f++) xv[f] = x[i * FIN + f];
#pragma unroll
        for (int h = 0; h < HH; h++) {
            float sum = acc[h] * inv;
#pragma unroll
            for (int f = 0; f < FIN; f++) sum += xv[f] * w[h * FIN + f];
            out[h] = sum;
        }
        norm_relu(out);
    }
    stats_block(out, 0, sstat);
    grid_sync(0);
    bn_params(0, sbn, sd);
    if (act) apply_tail(out, i, sbn, sg, sb, wl, outp, 1);
}

// ---------------- fused layers 2..5 (root from g_h) ----------------
__global__ void __launch_bounds__(256, 3) k_layer(
    const int* __restrict__ row, const int* __restrict__ cnt, const int* __restrict__ csr,
    const float* __restrict__ Wr, const float* __restrict__ gam, const float* __restrict__ bet,
    const float* __restrict__ Wlnext, float* __restrict__ outp, int layer, int writeZ)
{
    __shared__ float w[HH * HH], wl[HH * HH], sstat[16], sg[HH], sb[HH], sbn[16];
    __shared__ double sd[16];
    int tid = threadIdx.x;
    if (tid < HH * HH) w[tid] = Wr[tid];
    if (writeZ && tid < HH * HH) wl[tid] = Wlnext[tid];
    if (tid < 16) sstat[tid] = 0.f;
    if (tid < HH) { sg[tid] = gam[tid]; sb[tid] = bet[tid]; }
    __syncthreads();
    int i = blockIdx.x * blockDim.x + tid;
    bool act = i < NN;
    float out[HH];
#pragma unroll
    for (int h = 0; h < HH; h++) out[h] = 0.f;
    if (act) {
        int s = row[i], d = cnt[i];
        float acc[HH];
#pragma unroll
        for (int h = 0; h < HH; h++) acc[h] = 0.f;
        gather_row(s, d, csr, acc);
        float inv = 1.f / fmaxf((float)d, 1.f);
        float4 h0 = *(const float4*)&g_h[i * HH];
        float4 h1 = *(const float4*)&g_h[i * HH + 4];
        float hv[HH] = {h0.x, h0.y, h0.z, h0.w, h1.x, h1.y, h1.z, h1.w};
#pragma unroll
        for (int h = 0; h < HH; h++) {
            float sum = acc[h] * inv;
#pragma unroll
            for (int f = 0; f < HH; f++) sum += hv[f] * w[h * HH + f];
            out[h] = sum;
        }
        norm_relu(out);
    }
    stats_block(out, layer, sstat);
    grid_sync(layer);
    bn_params(layer, sbn, sd);
    if (act) apply_tail(out, i, sbn, sg, sb, wl, outp, writeZ);
}

// ---------------- host ----------------
extern "C" void kernel_launch(void* const* d_in, const int* in_sizes, int n_in,
                              void* d_out, int out_size) {
    const float* x   = (const float*)d_in[0];
    const void*  eic = d_in[1];
    const void*  eid = d_in[2];
    const float* W1l = (const float*)d_in[3];
    const float* W1r = (const float*)d_in[4];
    const float* W2l = (const float*)d_in[5];
    const float* W2r = (const float*)d_in[6];
    const float* W3l = (const float*)d_in[7];
    const float* W3r = (const float*)d_in[8];
    const float* W4l = (const float*)d_in[9];
    const float* W4r = (const float*)d_in[10];
    const float* g1 = (const float*)d_in[11]; const float* b1 = (const float*)d_in[12];
    const float* g2 = (const float*)d_in[13]; const float* b2 = (const float*)d_in[14];
    const float* g3 = (const float*)d_in[15]; const float* b3 = (const float*)d_in[16];
    const float* g4 = (const float*)d_in[17]; const float* b4 = (const float*)d_in[18];
    float* out = (float*)d_out;

    const int T = 256;
    const int gN  = (NN + T - 1) / T;          // 391 blocks; 3/SM residency forced
    const int gEC = (EC + T - 1) / T;
    const int gED = (ED + T - 1) / T;
    const int nbN = (NN + SB - 1) / SB;

    int* prc;   cudaGetSymbolAddress((void**)&prc, g_rowc);
    int* prd;   cudaGetSymbolAddress((void**)&prd, g_rowd);
    int* pcc;   cudaGetSymbolAddress((void**)&pcc, g_cntc);
    int* pcd;   cudaGetSymbolAddress((void**)&pcd, g_cntd);
    int* pcsrc; cudaGetSymbolAddress((void**)&pcsrc, g_csrc);
    int* pcsrd; cudaGetSymbolAddress((void**)&pcsrd, g_csrd);
    float* ph;  cudaGetSymbolAddress((void**)&ph, g_h);

    // ---- CSR build (padded rows) ----
    k_init<<<gN, T>>>();
    k_detect<<<1, 32>>>((const int*)eic);
    k_count<<<gEC + gED, T>>>(eic, eid, gEC);
    k_scan1<<<2 * nbN, SB>>>();
    k_scan2<<<2, 256>>>(nbN);
    k_scan3<<<2 * nbN, SB>>>();
    k_place<<<gEC + gED, T>>>(eic, eid, gEC);
    k_fill<<<2 * gN, T>>>(gN);
    k_z_first<<<gN, T>>>(x, W1l);

    // ---- fused layers (R8 structure + padded int4 gather) ----
    k_layer_first<<<gN, T>>>(x, W1r, g1, b1, W4l, ph);
    k_layer<<<gN, T>>>(prc, pcc, pcsrc, W4r, g2, b2, W2l, ph, 1, 1);
    k_layer<<<gN, T>>>(prd, pcd, pcsrd, W2r, g3, b3, W3l, ph, 2, 1);
    k_layer<<<gN, T>>>(prc, pcc, pcsrc, W3r, g4, b4, W3l, ph, 3, 1);
    k_layer<<<gN, T>>>(prc, pcc, pcsrc, W3r, g4, b4, nullptr, out, 4, 0);
}

// round 15
// speedup vs baseline: 1.7140x; 1.0202x over previous
#include <cuda_runtime.h>
#include <cuda_fp16.h>

#define NN 100000
#define EC 6400000
#define ED 400000
#define HH 8
#define FIN 5
#define BN_EPS 1e-5
#define L2_EPS 1e-12f
#define SB 512
#define NSLICE 8
#define FULLM 0xffffffffu
#define ECP (EC + 4 * NN)
#define EDP (ED + 4 * NN)

// ---------------- scratch ----------------
__device__ __align__(16) int g_csrc[ECP];    // padded CSR src lists (by dst)
__device__ __align__(16) int g_csrd[EDP];
__device__ int   g_cntc[NN];                 // true degrees
__device__ int   g_cntd[NN];
__device__ int   g_curc[NN];
__device__ int   g_curd[NN];
__device__ int   g_rowc[NN];                 // padded, 4-aligned row starts
__device__ int   g_rowd[NN];
__device__ int   g_bsumc[256];
__device__ int   g_bsumd[256];
__device__ __align__(16) __half g_zh[(NN + 1) * HH]; // fp16 payload; slot NN = zero sentinel
__device__ __align__(16) float  g_h[NN * HH];        // post-BN features
__device__ double   g_stats[5][NSLICE][16];
__device__ unsigned g_arrive[16];
__device__ int      g_mode;

// layer configuration, passed by value
struct Cfg {
    const int* row; const int* cnt; const int* csr;
    const float* Wr; const float* gam; const float* bet;
    const float* Wl;      // NEXT layer's payload weight (if writeZ)
    float* outp;
    int writeZ;
};
struct AllCfg { Cfg c[5]; };

// ---------------- init ----------------
__global__ void k_init() {
    int i = blockIdx.x * blockDim.x + threadIdx.x;
    if (i < NN) { g_cntc[i] = 0; g_cntd[i] = 0; g_curc[i] = 0; g_curd[i] = 0; }
    if (i < 5 * NSLICE * 16) ((double*)g_stats)[i] = 0.0;
    if (i < 16) g_arrive[i] = 0u;
    if (i < HH) g_zh[NN * HH + i] = __float2half(0.f);   // zero sentinel payload
}

// ---------------- int64 vs int32 edge dtype detection ----------------
__global__ void k_detect(const int* __restrict__ ei) {
    int lane = threadIdx.x;
    int v = ei[2 * lane + 1];
    unsigned ball = __ballot_sync(FULLM, v == 0);
    if (lane == 0) g_mode = (ball == FULLM) ? 1 : 0;
}

__device__ __forceinline__ void load_edge(const void* ei, int E, int e, int& src, int& dst) {
    if (g_mode) {
        const long long* p = (const long long*)ei;
        src = (int)p[e]; dst = (int)p[E + e];
    } else {
        const int* p = (const int*)ei;
        src = p[e]; dst = p[E + e];
    }
}

// ---------------- fused count over both edge sets ----------------
__global__ void k_count(const void* __restrict__ eic, const void* __restrict__ eid, int gEC) {
    long long b = blockIdx.x;
    if (b < gEC) {
        int e = (int)(b * blockDim.x + threadIdx.x);
        if (e < EC) {
            int src, dst; load_edge(eic, EC, e, src, dst);
            atomicAdd(&g_cntc[dst], 1);
        }
    } else {
        int e = (int)((b - gEC) * blockDim.x + threadIdx.x);
        if (e < ED) {
            int src, dst; load_edge(eid, ED, e, src, dst);
            atomicAdd(&g_cntd[dst], 1);
        }
    }
}

// ---------------- fused scans over PADDED counts ----------------
__global__ void k_scan1() {
    __shared__ int sh[SB];
    int half = gridDim.x >> 1;
    bool isC = blockIdx.x < half;
    const int* cnt = isC ? g_cntc : g_cntd;
    int* rowp = isC ? g_rowc : g_rowd;
    int* bsum = isC ? g_bsumc : g_bsumd;
    int b = isC ? blockIdx.x : blockIdx.x - half;
    int tid = threadIdx.x;
    int g = b * SB + tid;
    int v = (g < NN) ? ((cnt[g] + 3) & ~3) : 0;
    sh[tid] = v; __syncthreads();
#pragma unroll
    for (int o = 1; o < SB; o <<= 1) {
        int t = (tid >= o) ? sh[tid - o] : 0;
        __syncthreads();
        sh[tid] += t;
        __syncthreads();
    }
    if (g < NN) rowp[g] = sh[tid] - v;
    if (tid == SB - 1) bsum[b] = sh[SB - 1];
}
__global__ void k_scan2(int nb) {
    __shared__ int sh[256];
    int* bsum = (blockIdx.x == 0) ? g_bsumc : g_bsumd;
    int tid = threadIdx.x;
    int v = (tid < nb) ? bsum[tid] : 0;
    sh[tid] = v; __syncthreads();
#pragma unroll
    for (int o = 1; o < 256; o <<= 1) {
        int t = (tid >= o) ? sh[tid - o] : 0;
        __syncthreads();
        sh[tid] += t;
        __syncthreads();
    }
    if (tid < nb) bsum[tid] = sh[tid] - v;
}
__global__ void k_scan3() {
    int half = gridDim.x >> 1;
    bool isC = blockIdx.x < half;
    int* rowp = isC ? g_rowc : g_rowd;
    const int* bsum = isC ? g_bsumc : g_bsumd;
    int b = isC ? blockIdx.x : blockIdx.x - half;
    int g = b * SB + threadIdx.x;
    if (g < NN) rowp[g] += bsum[b];
}

// ---------------- fused CSR placement (cursor-based) ----------------
__global__ void k_place(const void* __restrict__ eic, const void* __restrict__ eid, int gEC) {
    long long b = blockIdx.x;
    if (b < gEC) {
        int e = (int)(b * blockDim.x + threadIdx.x);
        if (e < EC) {
            int src, dst; load_edge(eic, EC, e, src, dst);
            g_csrc[g_rowc[dst] + atomicAdd(&g_curc[dst], 1)] = src;
        }
    } else {
        int e = (int)((b - gEC) * blockDim.x + threadIdx.x);
        if (e < ED) {
            int src, dst; load_edge(eid, ED, e, src, dst);
            g_csrd[g_rowd[dst] + atomicAdd(&g_curd[dst], 1)] = src;
        }
    }
}

// ---------------- gather helpers ----------------
__device__ __forceinline__ void acc_payload(const uint4& a, float acc[HH]) {
    const __half2* ah = (const __half2*)&a;
#pragma unroll
    for (int k = 0; k < 4; k++) {
        float2 fa = __half22float2(ah[k]);
        acc[2 * k]     += fa.x;
        acc[2 * k + 1] += fa.y;
    }
}

// padded row: pure int4 index loads
__device__ __forceinline__ void gather_row(int s, int d, const int* __restrict__ csr,
                                           float acc[HH]) {
    int n4 = (d + 3) >> 2;
    const int4* ip = (const int4*)(csr + s);   // s is 4-aligned by construction
    for (int t = 0; t < n4; t++) {
        int4 id = __ldg(ip + t);
        uint4 a0 = __ldg((const uint4*)&g_zh[id.x * HH]);
        uint4 a1 = __ldg((const uint4*)&g_zh[id.y * HH]);
        uint4 a2 = __ldg((const uint4*)&g_zh[id.z * HH]);
        uint4 a3 = __ldg((const uint4*)&g_zh[id.w * HH]);
        acc_payload(a0, acc);
        acc_payload(a1, acc);
        acc_payload(a2, acc);
        acc_payload(a3, acc);
    }
}

// ---------------- block stats -> sliced global doubles ----------------
__device__ __forceinline__ void stats_block(const float out[HH], int layer, float* sstat) {
    int tid = threadIdx.x;
#pragma unroll
    for (int h = 0; h < HH; h++) {
        float s = out[h];
        float q = out[h] * out[h];
#pragma unroll
        for (int o = 16; o; o >>= 1) {
            s += __shfl_down_sync(FULLM, s, o);
            q += __shfl_down_sync(FULLM, q, o);
        }
        if ((tid & 31) == 0) {
            atomicAdd(&sstat[h], s);
            atomicAdd(&sstat[8 + h], q);
        }
    }
    __syncthreads();
    if (tid < 16) {
        atomicAdd(&g_stats[layer][blockIdx.x & (NSLICE - 1)][tid], (double)sstat[tid]);
        __threadfence();
    }
}

// ---------------- software grid sync (391 blocks; 3/SM forced by launch bounds) ----
__device__ __forceinline__ void grid_sync(int id) {
    __syncthreads();
    if (threadIdx.x == 0) {
        atomicAdd(&g_arrive[id], 1u);
        while (*(volatile unsigned*)&g_arrive[id] < gridDim.x) {}
        __threadfence();
    }
    __syncthreads();
}

__device__ __forceinline__ void bn_params(int layer, float* sbn, double* sd) {
    int tid = threadIdx.x;
    if (tid < 16) {
        double s = 0.0;
#pragma unroll
        for (int k = 0; k < NSLICE; k++) s += g_stats[layer][k][tid];
        sd[tid] = s;
    }
    __syncthreads();
    if (tid < 8) {
        double m = sd[tid] / (double)NN;
        double v = sd[8 + tid] / (double)NN - m * m;
        sbn[tid] = (float)m;
        sbn[8 + tid] = (float)rsqrt(v + BN_EPS);
    }
    __syncthreads();
}

__device__ __forceinline__ void norm_relu(float out[HH]) {
    float nrm = 0.f;
#pragma unroll
    for (int h = 0; h < HH; h++) nrm += out[h] * out[h];
    float invn = 1.f / fmaxf(sqrtf(nrm), L2_EPS);
#pragma unroll
    for (int h = 0; h < HH; h++) out[h] = fmaxf(out[h] * invn, 0.f);
}

__device__ __forceinline__ void apply_tail(const float out[HH], int i, const float* sbn,
                                           const float* sg, const float* sb, const float* wl,
                                           float* __restrict__ outp, int writeZ) {
    float hv[HH];
#pragma unroll
    for (int h = 0; h < HH; h++)
        hv[h] = (out[h] - sbn[h]) * sbn[8 + h] * sg[h] + sb[h];
    *(float4*)&outp[i * HH]     = make_float4(hv[0], hv[1], hv[2], hv[3]);
    *(float4*)&outp[i * HH + 4] = make_float4(hv[4], hv[5], hv[6], hv[7]);
    if (writeZ) {
        float z[HH];
#pragma unroll
        for (int h = 0; h < HH; h++) {
            float s = 0.f;
#pragma unroll
            for (int f = 0; f < HH; f++) s += hv[f] * wl[h * HH + f];
            z[h] = s;
        }
        __half2 zo[4];
#pragma unroll
        for (int k = 0; k < 4; k++) zo[k] = __floats2half2_rn(z[2 * k], z[2 * k + 1]);
        *(uint4*)&g_zh[i * HH] = *(uint4*)zo;
    }
}

// ---------------- ONE persistent mega-kernel: prologue + 5 fused layers ----------
__global__ void __launch_bounds__(256, 3) k_mega(
    const float* __restrict__ x, const float* __restrict__ W1l, AllCfg cfgs)
{
    __shared__ float w[HH * HH], wl[HH * HH], sstat[16], sg[HH], sb[HH], sbn[16];
    __shared__ double sd[16];
    int tid = threadIdx.x;
    int gid = blockIdx.x * blockDim.x + tid;
    int stride = gridDim.x * blockDim.x;

    // ---- prologue: CSR pad fill + z = x @ W1l^T ----
    if (tid < HH * FIN) w[tid] = W1l[tid];
    __syncthreads();
    for (int i = gid; i < NN; i += stride) {
        // pad fill (both CSRs)
        int d = g_cntc[i], s = g_rowc[i];
        int pad = (d + 3) & ~3;
        for (int j = d; j < pad; j++) g_csrc[s + j] = NN;
        d = g_cntd[i]; s = g_rowd[i];
        pad = (d + 3) & ~3;
        for (int j = d; j < pad; j++) g_csrd[s + j] = NN;
        // z_first
        float xv[FIN];
#pragma unroll
        for (int f = 0; f < FIN; f++) xv[f] = x[i * FIN + f];
        float z[HH];
#pragma unroll
        for (int h = 0; h < HH; h++) {
            float sum = 0.f;
#pragma unroll
            for (int f = 0; f < FIN; f++) sum += xv[f] * w[h * FIN + f];
            z[h] = sum;
        }
        __half2 zo[4];
#pragma unroll
        for (int k = 0; k < 4; k++) zo[k] = __floats2half2_rn(z[2 * k], z[2 * k + 1]);
        *(uint4*)&g_zh[i * HH] = *(uint4*)zo;
    }
    grid_sync(0);

    // ---- layer loop ----
    int i = gid;
    bool act = i < NN;
    for (int L = 0; L < 5; L++) {
        Cfg cfg = cfgs.c[L];
        int fdim = (L == 0) ? FIN : HH;
        if (tid < HH * fdim) w[tid] = cfg.Wr[tid];
        if (cfg.writeZ && tid < HH * HH) wl[tid] = cfg.Wl[tid];
        if (tid < 16) sstat[tid] = 0.f;
        if (tid < HH) { sg[tid] = cfg.gam[tid]; sb[tid] = cfg.bet[tid]; }
        __syncthreads();

        float out[HH];
#pragma unroll
        for (int h = 0; h < HH; h++) out[h] = 0.f;
        if (act) {
            int s = cfg.row[i], d = cfg.cnt[i];
            float acc[HH];
#pragma unroll
            for (int h = 0; h < HH; h++) acc[h] = 0.f;
            gather_row(s, d, cfg.csr, acc);
            float inv = 1.f / fmaxf((float)d, 1.f);
            if (L == 0) {
                float xv[FIN];
#pragma unroll
                for (int f = 0; f < FIN; f++) xv[f] = x[i * FIN + f];
#pragma unroll
                for (int h = 0; h < HH; h++) {
                    float sum = acc[h] * inv;
#pragma unroll
                    for (int f = 0; f < FIN; f++) sum += xv[f] * w[h * FIN + f];
                    out[h] = sum;
                }
            } else {
                float4 h0 = *(const float4*)&g_h[i * HH];
                float4 h1 = *(const float4*)&g_h[i * HH + 4];
                float hv[HH] = {h0.x, h0.y, h0.z, h0.w, h1.x, h1.y, h1.z, h1.w};
#pragma unroll
                for (int h = 0; h < HH; h++) {
                    float sum = acc[h] * inv;
#pragma unroll
                    for (int f = 0; f < HH; f++) sum += hv[f] * w[h * HH + f];
                    out[h] = sum;
                }
            }
            norm_relu(out);
        }
        stats_block(out, L, sstat);
        grid_sync(1 + 2 * L);
        bn_params(L, sbn, sd);
        if (act) apply_tail(out, i, sbn, sg, sb, wl, cfg.outp, cfg.writeZ);
        if (L < 4) grid_sync(2 + 2 * L);   // next layer's gather reads g_zh/g_h
    }
}

// ---------------- host ----------------
extern "C" void kernel_launch(void* const* d_in, const int* in_sizes, int n_in,
                              void* d_out, int out_size) {
    const float* x   = (const float*)d_in[0];
    const void*  eic = d_in[1];
    const void*  eid = d_in[2];
    const float* W1l = (const float*)d_in[3];
    const float* W1r = (const float*)d_in[4];
    const float* W2l = (const float*)d_in[5];
    const float* W2r = (const float*)d_in[6];
    const float* W3l = (const float*)d_in[7];
    const float* W3r = (const float*)d_in[8];
    const float* W4l = (const float*)d_in[9];
    const float* W4r = (const float*)d_in[10];
    const float* g1 = (const float*)d_in[11]; const float* b1 = (const float*)d_in[12];
    const float* g2 = (const float*)d_in[13]; const float* b2 = (const float*)d_in[14];
    const float* g3 = (const float*)d_in[15]; const float* b3 = (const float*)d_in[16];
    const float* g4 = (const float*)d_in[17]; const float* b4 = (const float*)d_in[18];
    float* out = (float*)d_out;

    const int T = 256;
    const int gN  = (NN + T - 1) / T;          // 391 blocks; 3/SM residency forced
    const int gEC = (EC + T - 1) / T;
    const int gED = (ED + T - 1) / T;
    const int nbN = (NN + SB - 1) / SB;

    int* prc;   cudaGetSymbolAddress((void**)&prc, g_rowc);
    int* prd;   cudaGetSymbolAddress((void**)&prd, g_rowd);
    int* pcc;   cudaGetSymbolAddress((void**)&pcc, g_cntc);
    int* pcd;   cudaGetSymbolAddress((void**)&pcd, g_cntd);
    int* pcsrc; cudaGetSymbolAddress((void**)&pcsrc, g_csrc);
    int* pcsrd; cudaGetSymbolAddress((void**)&pcsrd, g_csrd);
    float* ph;  cudaGetSymbolAddress((void**)&ph, g_h);

    // ---- CSR build (padded rows) ----
    k_init<<<gN, T>>>();
    k_detect<<<1, 32>>>((const int*)eic);
    k_count<<<gEC + gED, T>>>(eic, eid, gEC);
    k_scan1<<<2 * nbN, SB>>>();
    k_scan2<<<2, 256>>>(nbN);
    k_scan3<<<2 * nbN, SB>>>();
    k_place<<<gEC + gED, T>>>(eic, eid, gEC);

    // ---- one persistent kernel for prologue + all 5 layers ----
    AllCfg cf;
    // layer 1: conv1 + bn1 (next payload W4l)
    cf.c[0] = { prc, pcc, pcsrc, W1r, g1, b1, W4l, ph, 1 };
    // layer 2: conv4 + bn2 (next W2l)
    cf.c[1] = { prc, pcc, pcsrc, W4r, g2, b2, W2l, ph, 1 };
    // layer 3 (ED): conv2 + bn3 (next W3l)
    cf.c[2] = { prd, pcd, pcsrd, W2r, g3, b3, W3l, ph, 1 };
    // layer 4: conv3 + bn4 (next W3l)
    cf.c[3] = { prc, pcc, pcsrc, W3r, g4, b4, W3l, ph, 1 };
    // layer 5: conv3 + bn4 -> d_out
    cf.c[4] = { prc, pcc, pcsrc, W3r, g4, b4, nullptr, out, 0 };
    k_mega<<<gN, T>>>(x, W1l, cf);
}